// round 15
// baseline (speedup 1.0000x reference)
#include <cuda_runtime.h>
#include <cstdint>

// ScaleDotProductAttention: softmax(mask(QK^T*scale))V, B=8, QL=KL=2048, D=128 fp32.
// fp16 flash attention on mma.sync (HMMA): S = Qf16 K^T, O = Pf16 V.
// R15: warp-specialized. 8 compute warps + 1 producer warp staging K/V/mask
// through a 3-buffer ring with named-barrier (bar.arrive/bar.sync) handshakes.

#define QL_ 2048
#define D_  128
#define BK_ 64
#define NT_ 32
#define NTH 288
#define C_EXP 0.12751744750954205f   // log2(e)/sqrt(128)

// SMEM (bytes): rows of 128 fp16 = 256B, XOR-swizzled in 16B chunks.
#define OFF_Q   0                       // 128 rows x 256B = 32768
#define OFF_K0  32768                   // 3 x 16384
#define OFF_V0  81920                   // 3 x 16384
#define OFF_MSK 131072                  // 3 x 256B
#define SMEM_TOTAL (131072 + 768)

// named barriers: full[i] = 1+i, empty[i] = 4+i  (i = 0..2)
#define BAR_SYNC(id)   asm volatile("bar.sync %0, %1;"   :: "r"(id), "r"(NTH) : "memory")
#define BAR_ARRIVE(id) asm volatile("bar.arrive %0, %1;" :: "r"(id), "r"(NTH) : "memory")

__device__ __forceinline__ uint32_t smem_u32(const void* p) {
    uint32_t a;
    asm("{ .reg .u64 t; cvta.to.shared.u64 t, %1; cvt.u32.u64 %0, t; }" : "=r"(a) : "l"(p));
    return a;
}

// byte offset of (row, 16B-chunk) inside a [rows][128 fp16] tile, swizzled
__device__ __forceinline__ uint32_t tile_off(int row, int chunk) {
    return (uint32_t)(row * 256 + ((chunk ^ (row & 7)) << 4));
}

#define LDSM_X4(r, a)                                                            \
    asm volatile("ldmatrix.sync.aligned.m8n8.x4.shared.b16 {%0,%1,%2,%3}, [%4];" \
                 : "=r"((r)[0]), "=r"((r)[1]), "=r"((r)[2]), "=r"((r)[3]) : "r"(a))

#define LDSM_X4_T(r, a)                                                                \
    asm volatile("ldmatrix.sync.aligned.m8n8.x4.trans.shared.b16 {%0,%1,%2,%3}, [%4];" \
                 : "=r"((r)[0]), "=r"((r)[1]), "=r"((r)[2]), "=r"((r)[3]) : "r"(a))

#define MMA(c, a, b0, b1)                                                        \
    asm volatile("mma.sync.aligned.m16n8k16.row.col.f32.f16.f16.f32 "            \
                 "{%0,%1,%2,%3}, {%4,%5,%6,%7}, {%8,%9}, {%0,%1,%2,%3};"         \
                 : "+f"((c)[0]), "+f"((c)[1]), "+f"((c)[2]), "+f"((c)[3])        \
                 : "r"((a)[0]), "r"((a)[1]), "r"((a)[2]), "r"((a)[3]),           \
                   "r"(b0), "r"(b1))

__device__ __forceinline__ uint32_t f16x2(float hi, float lo) {
    uint32_t r;
    asm("cvt.rn.f16x2.f32 %0, %1, %2;" : "=r"(r) : "f"(hi), "f"(lo));
    return r;
}
__device__ __forceinline__ float ex2(float x) {
    float r;
    asm("ex2.approx.f32 %0, %1;" : "=f"(r) : "f"(x));
    return r;
}

// Q loader (256 compute threads): fp32 -> fp16 swizzled
__device__ __forceinline__ void load_q(const float* __restrict__ src, char* dst, int tid) {
    #pragma unroll
    for (int i = 0; i < 16; i++) {
        int e = tid + i * 256;
        int r = e >> 5;
        int d = (e & 31) << 2;
        float4 v = *(const float4*)(src + r * D_ + d);
        uint32_t a = f16x2(v.y, v.x);
        uint32_t b = f16x2(v.w, v.z);
        uint32_t off = (uint32_t)(r * 256) + ((((d >> 3) ^ (r & 7)) << 4)) + ((d & 4) << 1);
        *(uint2*)(dst + off) = make_uint2(a, b);
    }
}

// producer warp: convert one 64x128 fp32 tile -> fp16 swizzled (lane-parallel)
__device__ __forceinline__ void stage_tile(const float* __restrict__ src,
                                           char* dst, int lane) {
    #pragma unroll 8
    for (int i = 0; i < 64; i++) {
        float4 v = *(const float4*)(src + i * D_ + lane * 4);
        uint32_t a = f16x2(v.y, v.x);
        uint32_t b = f16x2(v.w, v.z);
        uint32_t off = (uint32_t)(i * 256) + ((((lane >> 1) ^ (i & 7)) << 4)) + ((lane & 1) << 3);
        *(uint2*)(dst + off) = make_uint2(a, b);
    }
}

extern __shared__ char smem[];

__global__ void __launch_bounds__(NTH, 1)
attn_mma_kernel(const float* __restrict__ qg, const float* __restrict__ kg,
                const float* __restrict__ vg, const int* __restrict__ maskg,
                float* __restrict__ outg)
{
    const int tid  = threadIdx.x;
    const int wid  = tid >> 5;
    const int lane = tid & 31;
    const int b    = blockIdx.y;
    const int q0   = blockIdx.x * 128;

    const float* kb = kg + (long)b * QL_ * D_;
    const float* vb = vg + (long)b * QL_ * D_;
    const int*   mb = maskg + (long)b * QL_;
    const uint32_t sb = smem_u32(smem);

    // Q staged by the 8 compute warps
    if (wid < 8)
        load_q(qg + ((long)b * QL_ + q0) * D_, smem + OFF_Q, tid);
    __syncthreads();

    if (wid == 8) {
        // ================= producer warp =================
        for (int t = 0; t < NT_; t++) {
            const int buf = t % 3;
            if (t >= 3) BAR_SYNC(4 + buf);          // wait until buffer consumed
            stage_tile(kb + (long)t * BK_ * D_, smem + OFF_K0 + buf * 16384, lane);
            stage_tile(vb + (long)t * BK_ * D_, smem + OFF_V0 + buf * 16384, lane);
            float* mf = (float*)(smem + OFF_MSK + buf * 256);
            mf[lane]      = (mb[t * BK_ + lane]      != 0) ? 1.0f : 0.0f;
            mf[lane + 32] = (mb[t * BK_ + 32 + lane] != 0) ? 1.0f : 0.0f;
            __threadfence_block();                  // STS visible before arrive
            BAR_ARRIVE(1 + buf);                    // publish buffer full
        }
        return;
    }

    // ================= compute warps =================
    const int gid = lane >> 2;
    const int tig = lane & 3;

    float o[16][4];
    #pragma unroll
    for (int n = 0; n < 16; n++)
        #pragma unroll
        for (int j = 0; j < 4; j++) o[n][j] = 0.0f;
    float lacc0 = 0.0f, lacc1 = 0.0f;

    for (int t = 0; t < NT_; t++) {
        const int buf = t % 3;
        BAR_SYNC(1 + buf);                          // wait buffer full
        const uint32_t kB = sb + OFF_K0 + buf * 16384;
        const uint32_t vB = sb + OFF_V0 + buf * 16384;
        const char* mskc = smem + OFF_MSK + buf * 256;

        // ---- GEMM1: S[16 x 64] = Q K^T ----
        float s[8][4];
        #pragma unroll
        for (int n = 0; n < 8; n++)
            #pragma unroll
            for (int j = 0; j < 4; j++) s[n][j] = 0.0f;

        #pragma unroll
        for (int ks = 0; ks < 8; ks++) {
            uint32_t ah[4];
            uint32_t aoff = tile_off(16 * wid + (lane & 15), 2 * ks + (lane >> 4));
            LDSM_X4(ah, sb + OFF_Q + aoff);
            #pragma unroll
            for (int np = 0; np < 4; np++) {
                uint32_t bh[4];
                uint32_t boff = tile_off(np * 16 + (lane & 7) + ((lane >> 4) << 3),
                                         2 * ks + ((lane >> 3) & 1));
                LDSM_X4(bh, kB + boff);
                MMA(s[2 * np],     ah, bh[0], bh[1]);
                MMA(s[2 * np + 1], ah, bh[2], bh[3]);
            }
        }

        // ---- softmax numerator: p = mask * exp2(dot*C); P -> fp16 A-frags ----
        uint32_t pH[16];
        #pragma unroll
        for (int j = 0; j < 8; j++) {
            float2 mv = *(float2*)(mskc + (8 * j + 2 * tig) * 4);
            float p0 = mv.x * ex2(s[j][0] * C_EXP);
            float p1 = mv.y * ex2(s[j][1] * C_EXP);
            float p2 = mv.x * ex2(s[j][2] * C_EXP);
            float p3 = mv.y * ex2(s[j][3] * C_EXP);
            lacc0 += p0 + p1;
            lacc1 += p2 + p3;
            int idx = (j >> 1) * 4 + (j & 1) * 2;
            pH[idx]     = f16x2(p1, p0);
            pH[idx + 1] = f16x2(p3, p2);
        }

        // ---- GEMM2: O[16 x 128] += P V  (V^T via ldmatrix.trans) ----
        #pragma unroll
        for (int ks = 0; ks < 4; ks++) {
            uint32_t* aH = &pH[ks * 4];
            #pragma unroll
            for (int np = 0; np < 8; np++) {
                uint32_t bh[4];
                uint32_t voff = tile_off(ks * 16 + (lane & 7) + (((lane >> 3) & 1) << 3),
                                         2 * np + (lane >> 4));
                LDSM_X4_T(bh, vB + voff);
                MMA(o[2 * np],     aH, bh[0], bh[1]);
                MMA(o[2 * np + 1], aH, bh[2], bh[3]);
            }
        }
        BAR_ARRIVE(4 + buf);                        // release buffer
    }

    // ---- finalize: row sums via quad shuffles, normalize, store ----
    lacc0 += __shfl_xor_sync(0xffffffffu, lacc0, 1);
    lacc0 += __shfl_xor_sync(0xffffffffu, lacc0, 2);
    lacc1 += __shfl_xor_sync(0xffffffffu, lacc1, 1);
    lacc1 += __shfl_xor_sync(0xffffffffu, lacc1, 2);
    float inv0 = 1.0f / lacc0;
    float inv1 = 1.0f / lacc1;

    float* out0 = outg + ((long)b * QL_ + q0 + 16 * wid + gid) * D_;
    float* out1 = out0 + 8 * D_;
    #pragma unroll
    for (int n = 0; n < 16; n++) {
        int col = 8 * n + 2 * tig;
        *(float2*)(out0 + col) = make_float2(o[n][0] * inv0, o[n][1] * inv0);
        *(float2*)(out1 + col) = make_float2(o[n][2] * inv1, o[n][3] * inv1);
    }
}

extern "C" void kernel_launch(void* const* d_in, const int* in_sizes, int n_in,
                              void* d_out, int out_size) {
    (void)in_sizes; (void)n_in; (void)out_size;
    const float* q = (const float*)d_in[0];
    const float* k = (const float*)d_in[1];
    const float* v = (const float*)d_in[2];
    const int* mask = (const int*)d_in[3];
    float* out = (float*)d_out;

    cudaFuncSetAttribute(attn_mma_kernel,
                         cudaFuncAttributeMaxDynamicSharedMemorySize, SMEM_TOTAL);

    dim3 grid(QL_ / 128, 8);
    attn_mma_kernel<<<grid, NTH, SMEM_TOTAL>>>(q, k, v, mask, out);
}

// round 16
// speedup vs baseline: 2.4008x; 2.4008x over previous
#include <cuda_runtime.h>
#include <cstdint>

// ScaleDotProductAttention: softmax(mask(QK^T*scale))V, B=8, QL=KL=2048, D=128 fp32.
// fp16 flash attention on mma.sync (HMMA): S = Qf16 K^T, O = Pf16 V.
// R16: pre-pass kernel converts Q/K/V->fp16 (and mask->float) into __device__
// scratch; main kernel streams K/V/mask tiles via cp.async (LDGSTS) directly
// into swizzled SMEM, double-buffered. Compute warps do zero staging work.

#define QL_ 2048
#define D_  128
#define BK_ 64
#define NT_ 32
#define C_EXP 0.12751744750954205f   // log2(e)/sqrt(128)

// fp16 scratch: 8*2048*128 fp16 = 4 MB each, stored as uint2 (8B = 4 fp16)
__device__ uint2 gQ16[524288];
__device__ uint2 gK16[524288];
__device__ uint2 gV16[524288];
__device__ float gMsk[16384];

// SMEM (bytes): rows of 128 fp16 = 256B, XOR-swizzled in 16B chunks.
#define OFF_Q   0                      // 128 x 256B
#define OFF_K0  32768                  // 2 x 16384
#define OFF_V0  65536                  // 2 x 16384
#define OFF_MSK 98304                  // 2 x 256B
#define SMEM_TOTAL (98304 + 512)

__device__ __forceinline__ uint32_t smem_u32(const void* p) {
    uint32_t a;
    asm("{ .reg .u64 t; cvta.to.shared.u64 t, %1; cvt.u32.u64 %0, t; }" : "=r"(a) : "l"(p));
    return a;
}

// byte offset of (row, 16B-chunk) inside a [rows][128 fp16] tile, swizzled
__device__ __forceinline__ uint32_t tile_off(int row, int chunk) {
    return (uint32_t)(row * 256 + ((chunk ^ (row & 7)) << 4));
}

#define CP_ASYNC(dst, src)                                                       \
    asm volatile("cp.async.cg.shared.global [%0], [%1], 16;"                     \
                 :: "r"(dst), "l"(src) : "memory")
#define CP_COMMIT() asm volatile("cp.async.commit_group;" ::: "memory")
#define CP_WAIT0()  asm volatile("cp.async.wait_group 0;" ::: "memory")

#define LDSM_X4(r, a)                                                            \
    asm volatile("ldmatrix.sync.aligned.m8n8.x4.shared.b16 {%0,%1,%2,%3}, [%4];" \
                 : "=r"((r)[0]), "=r"((r)[1]), "=r"((r)[2]), "=r"((r)[3]) : "r"(a))

#define LDSM_X4_T(r, a)                                                                \
    asm volatile("ldmatrix.sync.aligned.m8n8.x4.trans.shared.b16 {%0,%1,%2,%3}, [%4];" \
                 : "=r"((r)[0]), "=r"((r)[1]), "=r"((r)[2]), "=r"((r)[3]) : "r"(a))

#define MMA(c, a, b0, b1)                                                        \
    asm volatile("mma.sync.aligned.m16n8k16.row.col.f32.f16.f16.f32 "            \
                 "{%0,%1,%2,%3}, {%4,%5,%6,%7}, {%8,%9}, {%0,%1,%2,%3};"         \
                 : "+f"((c)[0]), "+f"((c)[1]), "+f"((c)[2]), "+f"((c)[3])        \
                 : "r"((a)[0]), "r"((a)[1]), "r"((a)[2]), "r"((a)[3]),           \
                   "r"(b0), "r"(b1))

__device__ __forceinline__ uint32_t f16x2(float hi, float lo) {
    uint32_t r;
    asm("cvt.rn.f16x2.f32 %0, %1, %2;" : "=r"(r) : "f"(hi), "f"(lo));
    return r;
}
__device__ __forceinline__ float ex2(float x) {
    float r;
    asm("ex2.approx.f32 %0, %1;" : "=f"(r) : "f"(x));
    return r;
}

// ---------------- pre-pass: fp32 -> fp16 scratch (+ mask -> float) ----------------
__global__ void __launch_bounds__(256, 4)
cvt_pre(const float* __restrict__ q, const float* __restrict__ k,
        const float* __restrict__ v, const int* __restrict__ m)
{
    const int idx = blockIdx.x * 256 + threadIdx.x;      // 0 .. 524287
    const int sel = blockIdx.y;
    const float4* src = (const float4*)(sel == 0 ? q : (sel == 1 ? k : v));
    uint2* dst = (sel == 0 ? gQ16 : (sel == 1 ? gK16 : gV16));
    float4 vv = src[idx];
    uint2 r;
    r.x = f16x2(vv.y, vv.x);
    r.y = f16x2(vv.w, vv.z);
    dst[idx] = r;
    if (sel == 0 && idx < 16384)
        gMsk[idx] = (m[idx] != 0) ? 1.0f : 0.0f;
}

// issue cp.async for one 64x128 fp16 K/V tile pair + mask into a buffer
__device__ __forceinline__ void issue_tile(int b, int t, uint32_t kD, uint32_t vD,
                                           uint32_t mD, int tid)
{
    const char* ks = (const char*)gK16 + ((long)b * QL_ + t * BK_) * 256;
    const char* vs = (const char*)gV16 + ((long)b * QL_ + t * BK_) * 256;
    #pragma unroll
    for (int i = 0; i < 4; i++) {
        int c = tid + i * 256;          // 0..1023: row = c>>4, chunk = c&15
        uint32_t off = tile_off(c >> 4, c & 15);
        CP_ASYNC(kD + off, ks + c * 16);
        CP_ASYNC(vD + off, vs + c * 16);
    }
    if (tid < 16)
        CP_ASYNC(mD + tid * 16,
                 (const char*)gMsk + ((long)b * QL_ + t * BK_) * 4 + tid * 16);
}

extern __shared__ char smem[];

__global__ void __launch_bounds__(256, 1)
attn_mma_kernel(float* __restrict__ outg)
{
    const int tid  = threadIdx.x;
    const int wid  = tid >> 5;
    const int lane = tid & 31;
    const int gid  = lane >> 2;
    const int tig  = lane & 3;
    const int b    = blockIdx.y;
    const int q0   = blockIdx.x * 128;
    const uint32_t sb = smem_u32(smem);

    // Q tile (already fp16): cp.async into swizzled smem, bundled with tile 0
    {
        const char* qs = (const char*)gQ16 + ((long)b * QL_ + q0) * 256;
        #pragma unroll
        for (int i = 0; i < 8; i++) {
            int c = tid + i * 256;      // 0..2047: row = c>>4, chunk = c&15
            CP_ASYNC(sb + OFF_Q + tile_off(c >> 4, c & 15), qs + c * 16);
        }
    }
    issue_tile(b, 0, sb + OFF_K0, sb + OFF_V0, sb + OFF_MSK, tid);
    CP_COMMIT();

    float o[16][4];
    #pragma unroll
    for (int n = 0; n < 16; n++)
        #pragma unroll
        for (int j = 0; j < 4; j++) o[n][j] = 0.0f;
    float lacc0 = 0.0f, lacc1 = 0.0f;

    CP_WAIT0();
    __syncthreads();

    for (int t = 0; t < NT_; t++) {
        const int cur = t & 1;
        const uint32_t kB = sb + OFF_K0 + cur * 16384;
        const uint32_t vB = sb + OFF_V0 + cur * 16384;
        const char* mskc = smem + OFF_MSK + cur * 256;

        // DMA for tile t+1 into the other buffer (flies under this tile's compute)
        if (t + 1 < NT_) {
            const int nxt = cur ^ 1;
            issue_tile(b, t + 1, sb + OFF_K0 + nxt * 16384,
                       sb + OFF_V0 + nxt * 16384, sb + OFF_MSK + nxt * 256, tid);
            CP_COMMIT();
        }

        // ---- GEMM1: S[16 x 64] = Q K^T ----
        float s[8][4];
        #pragma unroll
        for (int n = 0; n < 8; n++)
            #pragma unroll
            for (int j = 0; j < 4; j++) s[n][j] = 0.0f;

        #pragma unroll
        for (int ks = 0; ks < 8; ks++) {
            uint32_t ah[4];
            uint32_t aoff = tile_off(16 * wid + (lane & 15), 2 * ks + (lane >> 4));
            LDSM_X4(ah, sb + OFF_Q + aoff);
            #pragma unroll
            for (int np = 0; np < 4; np++) {
                uint32_t bh[4];
                uint32_t boff = tile_off(np * 16 + (lane & 7) + ((lane >> 4) << 3),
                                         2 * ks + ((lane >> 3) & 1));
                LDSM_X4(bh, kB + boff);
                MMA(s[2 * np],     ah, bh[0], bh[1]);
                MMA(s[2 * np + 1], ah, bh[2], bh[3]);
            }
        }

        // ---- softmax numerator: p = mask * exp2(dot*C); P -> fp16 A-frags ----
        uint32_t pH[16];
        #pragma unroll
        for (int j = 0; j < 8; j++) {
            float2 mv = *(float2*)(mskc + (8 * j + 2 * tig) * 4);
            float p0 = mv.x * ex2(s[j][0] * C_EXP);
            float p1 = mv.y * ex2(s[j][1] * C_EXP);
            float p2 = mv.x * ex2(s[j][2] * C_EXP);
            float p3 = mv.y * ex2(s[j][3] * C_EXP);
            lacc0 += p0 + p1;
            lacc1 += p2 + p3;
            int idx = (j >> 1) * 4 + (j & 1) * 2;
            pH[idx]     = f16x2(p1, p0);
            pH[idx + 1] = f16x2(p3, p2);
        }

        // ---- GEMM2: O[16 x 128] += P V  (V^T via ldmatrix.trans) ----
        #pragma unroll
        for (int ks = 0; ks < 4; ks++) {
            uint32_t* aH = &pH[ks * 4];
            #pragma unroll
            for (int np = 0; np < 8; np++) {
                uint32_t bh[4];
                uint32_t voff = tile_off(ks * 16 + (lane & 7) + (((lane >> 3) & 1) << 3),
                                         2 * np + (lane >> 4));
                LDSM_X4_T(bh, vB + voff);
                MMA(o[2 * np],     aH, bh[0], bh[1]);
                MMA(o[2 * np + 1], aH, bh[2], bh[3]);
            }
        }

        // tile t+1 DMA must land; all warps past buffer before overwrite next iter
        if (t + 1 < NT_) CP_WAIT0();
        __syncthreads();
    }

    // ---- finalize: row sums via quad shuffles, normalize, store ----
    lacc0 += __shfl_xor_sync(0xffffffffu, lacc0, 1);
    lacc0 += __shfl_xor_sync(0xffffffffu, lacc0, 2);
    lacc1 += __shfl_xor_sync(0xffffffffu, lacc1, 1);
    lacc1 += __shfl_xor_sync(0xffffffffu, lacc1, 2);
    float inv0 = 1.0f / lacc0;
    float inv1 = 1.0f / lacc1;

    float* out0 = outg + ((long)b * QL_ + q0 + 16 * wid + gid) * D_;
    float* out1 = out0 + 8 * D_;
    #pragma unroll
    for (int n = 0; n < 16; n++) {
        int col = 8 * n + 2 * tig;
        *(float2*)(out0 + col) = make_float2(o[n][0] * inv0, o[n][1] * inv0);
        *(float2*)(out1 + col) = make_float2(o[n][2] * inv1, o[n][3] * inv1);
    }
}

extern "C" void kernel_launch(void* const* d_in, const int* in_sizes, int n_in,
                              void* d_out, int out_size) {
    (void)in_sizes; (void)n_in; (void)out_size;
    const float* q = (const float*)d_in[0];
    const float* k = (const float*)d_in[1];
    const float* v = (const float*)d_in[2];
    const int* mask = (const int*)d_in[3];
    float* out = (float*)d_out;

    // pre-pass: fp32 -> fp16 scratch (Q/K/V) + mask -> float
    dim3 pgrid(2048, 3);
    cvt_pre<<<pgrid, 256>>>(q, k, v, mask);

    cudaFuncSetAttribute(attn_mma_kernel,
                         cudaFuncAttributeMaxDynamicSharedMemorySize, SMEM_TOTAL);
    dim3 grid(QL_ / 128, 8);
    attn_mma_kernel<<<grid, 256, SMEM_TOTAL>>>(out);
}

// round 17
// speedup vs baseline: 2.5083x; 1.0448x over previous
#include <cuda_runtime.h>
#include <cstdint>

// ScaleDotProductAttention: softmax(mask(QK^T*scale))V, B=8, QL=KL=2048, D=128 fp32.
// fp16 flash attention on mma.sync (HMMA): S = Qf16 K^T, O = Pf16 V.
// R17: R16 (fp16 pre-pass + cp.async staging) with BM=64 / 128-thread CTAs and
// 2 CTAs per SM — independent barrier domains overlap softmax/sync bubbles.

#define QL_ 2048
#define D_  128
#define BK_ 64
#define NT_ 32
#define NTH 128
#define C_EXP 0.12751744750954205f   // log2(e)/sqrt(128)

// fp16 scratch: 8*2048*128 fp16 = 4 MB each, stored as uint2 (8B = 4 fp16)
__device__ uint2 gQ16[524288];
__device__ uint2 gK16[524288];
__device__ uint2 gV16[524288];
__device__ float gMsk[16384];

// SMEM (bytes): rows of 128 fp16 = 256B, XOR-swizzled in 16B chunks.
#define OFF_Q   0                      // 64 x 256B = 16384
#define OFF_K0  16384                  // 2 x 16384
#define OFF_V0  49152                  // 2 x 16384
#define OFF_MSK 81920                  // 2 x 256B
#define SMEM_TOTAL (81920 + 512)

__device__ __forceinline__ uint32_t smem_u32(const void* p) {
    uint32_t a;
    asm("{ .reg .u64 t; cvta.to.shared.u64 t, %1; cvt.u32.u64 %0, t; }" : "=r"(a) : "l"(p));
    return a;
}

// byte offset of (row, 16B-chunk) inside a [rows][128 fp16] tile, swizzled
__device__ __forceinline__ uint32_t tile_off(int row, int chunk) {
    return (uint32_t)(row * 256 + ((chunk ^ (row & 7)) << 4));
}

#define CP_ASYNC(dst, src)                                                       \
    asm volatile("cp.async.cg.shared.global [%0], [%1], 16;"                     \
                 :: "r"(dst), "l"(src) : "memory")
#define CP_COMMIT() asm volatile("cp.async.commit_group;" ::: "memory")
#define CP_WAIT0()  asm volatile("cp.async.wait_group 0;" ::: "memory")

#define LDSM_X4(r, a)                                                            \
    asm volatile("ldmatrix.sync.aligned.m8n8.x4.shared.b16 {%0,%1,%2,%3}, [%4];" \
                 : "=r"((r)[0]), "=r"((r)[1]), "=r"((r)[2]), "=r"((r)[3]) : "r"(a))

#define LDSM_X4_T(r, a)                                                                \
    asm volatile("ldmatrix.sync.aligned.m8n8.x4.trans.shared.b16 {%0,%1,%2,%3}, [%4];" \
                 : "=r"((r)[0]), "=r"((r)[1]), "=r"((r)[2]), "=r"((r)[3]) : "r"(a))

#define MMA(c, a, b0, b1)                                                        \
    asm volatile("mma.sync.aligned.m16n8k16.row.col.f32.f16.f16.f32 "            \
                 "{%0,%1,%2,%3}, {%4,%5,%6,%7}, {%8,%9}, {%0,%1,%2,%3};"         \
                 : "+f"((c)[0]), "+f"((c)[1]), "+f"((c)[2]), "+f"((c)[3])        \
                 : "r"((a)[0]), "r"((a)[1]), "r"((a)[2]), "r"((a)[3]),           \
                   "r"(b0), "r"(b1))

__device__ __forceinline__ uint32_t f16x2(float hi, float lo) {
    uint32_t r;
    asm("cvt.rn.f16x2.f32 %0, %1, %2;" : "=r"(r) : "f"(hi), "f"(lo));
    return r;
}
__device__ __forceinline__ float ex2(float x) {
    float r;
    asm("ex2.approx.f32 %0, %1;" : "=f"(r) : "f"(x));
    return r;
}

// ---------------- pre-pass: fp32 -> fp16 scratch (+ mask -> float) ----------------
__global__ void __launch_bounds__(256, 4)
cvt_pre(const float* __restrict__ q, const float* __restrict__ k,
        const float* __restrict__ v, const int* __restrict__ m)
{
    const int idx = blockIdx.x * 256 + threadIdx.x;      // 0 .. 524287
    const int sel = blockIdx.y;
    const float4* src = (const float4*)(sel == 0 ? q : (sel == 1 ? k : v));
    uint2* dst = (sel == 0 ? gQ16 : (sel == 1 ? gK16 : gV16));
    float4 vv = src[idx];
    uint2 r;
    r.x = f16x2(vv.y, vv.x);
    r.y = f16x2(vv.w, vv.z);
    dst[idx] = r;
    if (sel == 0 && idx < 16384)
        gMsk[idx] = (m[idx] != 0) ? 1.0f : 0.0f;
}

// issue cp.async for one 64x128 fp16 K/V tile pair + mask into a buffer
__device__ __forceinline__ void issue_tile(int b, int t, uint32_t kD, uint32_t vD,
                                           uint32_t mD, int tid)
{
    const char* ks = (const char*)gK16 + ((long)b * QL_ + t * BK_) * 256;
    const char* vs = (const char*)gV16 + ((long)b * QL_ + t * BK_) * 256;
    #pragma unroll
    for (int i = 0; i < 8; i++) {
        int c = tid + i * NTH;          // 0..1023: row = c>>4, chunk = c&15
        uint32_t off = tile_off(c >> 4, c & 15);
        CP_ASYNC(kD + off, ks + c * 16);
        CP_ASYNC(vD + off, vs + c * 16);
    }
    if (tid < 16)
        CP_ASYNC(mD + tid * 16,
                 (const char*)gMsk + ((long)b * QL_ + t * BK_) * 4 + tid * 16);
}

extern __shared__ char smem[];

__global__ void __launch_bounds__(NTH, 2)
attn_mma_kernel(float* __restrict__ outg)
{
    const int tid  = threadIdx.x;
    const int wid  = tid >> 5;        // 0..3
    const int lane = tid & 31;
    const int gid  = lane >> 2;
    const int tig  = lane & 3;
    const int b    = blockIdx.y;
    const int q0   = blockIdx.x * 64;
    const uint32_t sb = smem_u32(smem);

    // Q tile (already fp16): cp.async into swizzled smem, bundled with tile 0
    {
        const char* qs = (const char*)gQ16 + ((long)b * QL_ + q0) * 256;
        #pragma unroll
        for (int i = 0; i < 8; i++) {
            int c = tid + i * NTH;      // 0..1023: row = c>>4, chunk = c&15
            CP_ASYNC(sb + OFF_Q + tile_off(c >> 4, c & 15), qs + c * 16);
        }
    }
    issue_tile(b, 0, sb + OFF_K0, sb + OFF_V0, sb + OFF_MSK, tid);
    CP_COMMIT();

    float o[16][4];
    #pragma unroll
    for (int n = 0; n < 16; n++)
        #pragma unroll
        for (int j = 0; j < 4; j++) o[n][j] = 0.0f;
    float lacc0 = 0.0f, lacc1 = 0.0f;

    CP_WAIT0();
    __syncthreads();

    for (int t = 0; t < NT_; t++) {
        const int cur = t & 1;
        const uint32_t kB = sb + OFF_K0 + cur * 16384;
        const uint32_t vB = sb + OFF_V0 + cur * 16384;
        const char* mskc = smem + OFF_MSK + cur * 256;

        // DMA for tile t+1 into the other buffer (flies under this tile's compute)
        if (t + 1 < NT_) {
            const int nxt = cur ^ 1;
            issue_tile(b, t + 1, sb + OFF_K0 + nxt * 16384,
                       sb + OFF_V0 + nxt * 16384, sb + OFF_MSK + nxt * 256, tid);
            CP_COMMIT();
        }

        // ---- GEMM1: S[16 x 64] = Q K^T ----
        float s[8][4];
        #pragma unroll
        for (int n = 0; n < 8; n++)
            #pragma unroll
            for (int j = 0; j < 4; j++) s[n][j] = 0.0f;

        #pragma unroll
        for (int ks = 0; ks < 8; ks++) {
            uint32_t ah[4];
            uint32_t aoff = tile_off(16 * wid + (lane & 15), 2 * ks + (lane >> 4));
            LDSM_X4(ah, sb + OFF_Q + aoff);
            #pragma unroll
            for (int np = 0; np < 4; np++) {
                uint32_t bh[4];
                uint32_t boff = tile_off(np * 16 + (lane & 7) + ((lane >> 4) << 3),
                                         2 * ks + ((lane >> 3) & 1));
                LDSM_X4(bh, kB + boff);
                MMA(s[2 * np],     ah, bh[0], bh[1]);
                MMA(s[2 * np + 1], ah, bh[2], bh[3]);
            }
        }

        // ---- softmax numerator: p = mask * exp2(dot*C); P -> fp16 A-frags ----
        uint32_t pH[16];
        #pragma unroll
        for (int j = 0; j < 8; j++) {
            float2 mv = *(float2*)(mskc + (8 * j + 2 * tig) * 4);
            float p0 = mv.x * ex2(s[j][0] * C_EXP);
            float p1 = mv.y * ex2(s[j][1] * C_EXP);
            float p2 = mv.x * ex2(s[j][2] * C_EXP);
            float p3 = mv.y * ex2(s[j][3] * C_EXP);
            lacc0 += p0 + p1;
            lacc1 += p2 + p3;
            int idx = (j >> 1) * 4 + (j & 1) * 2;
            pH[idx]     = f16x2(p1, p0);
            pH[idx + 1] = f16x2(p3, p2);
        }

        // ---- GEMM2: O[16 x 128] += P V  (V^T via ldmatrix.trans) ----
        #pragma unroll
        for (int ks = 0; ks < 4; ks++) {
            uint32_t* aH = &pH[ks * 4];
            #pragma unroll
            for (int np = 0; np < 8; np++) {
                uint32_t bh[4];
                uint32_t voff = tile_off(ks * 16 + (lane & 7) + (((lane >> 3) & 1) << 3),
                                         2 * np + (lane >> 4));
                LDSM_X4_T(bh, vB + voff);
                MMA(o[2 * np],     aH, bh[0], bh[1]);
                MMA(o[2 * np + 1], aH, bh[2], bh[3]);
            }
        }

        // tile t+1 DMA must land; all warps past buffer before overwrite next iter
        if (t + 1 < NT_) CP_WAIT0();
        __syncthreads();
    }

    // ---- finalize: row sums via quad shuffles, normalize, store ----
    lacc0 += __shfl_xor_sync(0xffffffffu, lacc0, 1);
    lacc0 += __shfl_xor_sync(0xffffffffu, lacc0, 2);
    lacc1 += __shfl_xor_sync(0xffffffffu, lacc1, 1);
    lacc1 += __shfl_xor_sync(0xffffffffu, lacc1, 2);
    float inv0 = 1.0f / lacc0;
    float inv1 = 1.0f / lacc1;

    float* out0 = outg + ((long)b * QL_ + q0 + 16 * wid + gid) * D_;
    float* out1 = out0 + 8 * D_;
    #pragma unroll
    for (int n = 0; n < 16; n++) {
        int col = 8 * n + 2 * tig;
        *(float2*)(out0 + col) = make_float2(o[n][0] * inv0, o[n][1] * inv0);
        *(float2*)(out1 + col) = make_float2(o[n][2] * inv1, o[n][3] * inv1);
    }
}

extern "C" void kernel_launch(void* const* d_in, const int* in_sizes, int n_in,
                              void* d_out, int out_size) {
    (void)in_sizes; (void)n_in; (void)out_size;
    const float* q = (const float*)d_in[0];
    const float* k = (const float*)d_in[1];
    const float* v = (const float*)d_in[2];
    const int* mask = (const int*)d_in[3];
    float* out = (float*)d_out;

    // pre-pass: fp32 -> fp16 scratch (Q/K/V) + mask -> float
    dim3 pgrid(2048, 3);
    cvt_pre<<<pgrid, 256>>>(q, k, v, mask);

    cudaFuncSetAttribute(attn_mma_kernel,
                         cudaFuncAttributeMaxDynamicSharedMemorySize, SMEM_TOTAL);
    dim3 grid(QL_ / 64, 8);
    attn_mma_kernel<<<grid, NTH, SMEM_TOTAL>>>(out);
}